// round 11
// baseline (speedup 1.0000x reference)
#include <cuda_runtime.h>
#include <cuda_bf16.h>
#include <math.h>

// ---------------- problem constants ----------------
#define BATCH 8
#define NN    512
#define DIN   64
#define HH    8
#define FF    128
#define LL    2
#define NEGV  (-9e15f)
#define LOG2E 1.4426950408889634f

// ---------------- scratch (device globals; no allocs) ----------------
__device__ float g_h    [BATCH * NN * FF];
__device__ float g_hh   [BATCH * HH * NN * FF];
__device__ float g_multi[BATCH * NN * HH * FF];
__device__ float g_h2   [BATCH * NN * FF];
__device__ float g_part [2 * BATCH * HH * NN * FF];   // split partials (gemm3 S=2 is the largest user)
__device__ float g_s1   [BATCH * HH * NN];
__device__ float g_s2   [BATCH * HH * NN];
__device__ float g_a1   [BATCH * HH * NN];            // (s1-mx)*log2e - log2(sum)
__device__ float g_b1   [BATCH * HH * NN];            // (0.2 s1-mx)*log2e - log2(sum)
__device__ float g_s2l  [BATCH * HH * NN];            // s2*log2e
__device__ float g_t1   [BATCH * NN];
__device__ float g_t2   [BATCH * NN];

// ---------------- reductions ----------------
__device__ __forceinline__ float warpSum(float v) {
#pragma unroll
    for (int o = 16; o > 0; o >>= 1) v += __shfl_xor_sync(0xffffffffu, v, o);
    return v;
}
__device__ __forceinline__ float warpMax(float v) {
#pragma unroll
    for (int o = 16; o > 0; o >>= 1) v = fmaxf(v, __shfl_xor_sync(0xffffffffu, v, o));
    return v;
}
__device__ __forceinline__ float blockSum128(float v) {
    __shared__ float sh[4];
    v = warpSum(v);
    __syncthreads();
    if ((threadIdx.x & 31) == 0) sh[threadIdx.x >> 5] = v;
    __syncthreads();
    return sh[0] + sh[1] + sh[2] + sh[3];
}
__device__ __forceinline__ float blockMax128(float v) {
    __shared__ float sh[4];
    v = warpMax(v);
    __syncthreads();
    if ((threadIdx.x & 31) == 0) sh[threadIdx.x >> 5] = v;
    __syncthreads();
    return fmaxf(fmaxf(sh[0], sh[1]), fmaxf(sh[2], sh[3]));
}

// ---------------- tf32 RNA rounding (bit trick == cvt.rna.tf32) ----------------
__device__ __forceinline__ unsigned rtf(float f) {
    return __float_as_uint(f) + 0x1000u;   // exact-0 stays 0 after 19-bit truncation
}
__device__ __forceinline__ void mma_tf32(float c[4], const unsigned a[4], const unsigned b0, const unsigned b1) {
    asm("mma.sync.aligned.m16n8k8.row.col.f32.tf32.tf32.f32 "
        "{%0,%1,%2,%3},{%4,%5,%6,%7},{%8,%9},{%0,%1,%2,%3};"
        : "+f"(c[0]), "+f"(c[1]), "+f"(c[2]), "+f"(c[3])
        : "r"(a[0]), "r"(a[1]), "r"(a[2]), "r"(a[3]), "r"(b0), "r"(b1));
}
__device__ __forceinline__ float ex2f(float x) {
    float r;
    asm("ex2.approx.f32 %0, %1;" : "=f"(r) : "f"(x));
    return r;
}
// att element in log2 domain: adj>0 ? ex2(max(A1+s2l, fma(0.2,s2l,B1))) : 0
__device__ __forceinline__ unsigned att_val(int aj, float s2l, float A1, float B1) {
    const float arg = fmaxf(A1 + s2l, fmaf(0.2f, s2l, B1));
    const float r = (aj > 0) ? ex2f(arg) : 0.f;
    return rtf(r);
}

// ---------------- input projection ----------------
__global__ void k_proj(const float* __restrict__ x, const float* __restrict__ Wp,
                       const float* __restrict__ bp, float* __restrict__ h) {
    __shared__ float xs[DIN];
    const int row = blockIdx.x;
    const int t = threadIdx.x;
    if (t < DIN) xs[t] = x[(long)row * DIN + t];
    __syncthreads();
    float acc = bp[t];
#pragma unroll
    for (int i = 0; i < DIN; i++) acc = fmaf(xs[i], Wp[i * FF + t], acc);
    h[(long)row * FF + t] = fmaxf(acc, 0.f);
}

// ---------------- pipelined TF32 tensor-core GEMM ----------------
// C[M,128] = A[M,KC*S] @ B[KC*S,128], row-major, ldb = 128.
// Block tile 128x128, K-step 16, double-buffered smem, 8 warps 4(M)x2(N).
// EPI: 0 none, 1 ELU, 2 plain + fused svec. ATT: 1 = A computed from log2 att factors.
#define GBM 128
#define GBK 16
#define ALD 24
#define BLD 136
template <int KC, int S, int EPI, int ATT>
__global__ __launch_bounds__(256, 2)
void k_gemm_t(const float* __restrict__ A, const float* __restrict__ B,
              float* __restrict__ C, float* __restrict__ Cpart,
              int M,
              long long sAb, long long sAh,
              long long sBb, long long sBh,
              long long sCb, long long sCh,
              int Hb, int ldc, long long TOT,
              const int* __restrict__ adj,
              const float* __restrict__ a1p, const float* __restrict__ b1p,
              const float* __restrict__ s2lp,
              const float* __restrict__ avec,
              float* __restrict__ o1, float* __restrict__ o2) {
    const int zz = blockIdx.z;
    const int s = zz % S;
    const int z2 = zz / S;
    const int bz = z2 / Hb, hz = z2 % Hb;
    A += bz * sAb + hz * sAh + (long long)s * KC;
    B += bz * sBb + hz * sBh + (long long)s * KC * 128;
    C += bz * sCb + hz * sCh;
    const int bm = blockIdx.y * GBM;
    constexpr long long Kfull = (long long)KC * S;
    const int soff = s * KC;

    __shared__ unsigned As[2][GBM][ALD];   // [m][perm_k]
    __shared__ unsigned Bs[2][GBK][BLD];   // [k][perm_n]
    __shared__ float ash[2 * FF];          // EPI==2
    __shared__ float sv1[GBM], sv2[GBM];   // EPI==2

    const int tid  = threadIdx.x;
    const int lane = tid & 31;
    const int wid  = tid >> 5;
    const int wm = (wid & 3) * 32;
    const int wn = (wid >> 2) * 64;
    const int q = lane & 3;
    const int g = lane >> 2;

    const int arow0 = tid >> 2;
    const int ac = tid & 3;
    const int aw0 = (ac & 1) + 8 * (ac >> 1);
    const int br = tid >> 5;
    const int bc = lane * 4;

    if (EPI == 2 && tid < 2 * FF) ash[tid] = (avec + (long long)hz * 2 * FF)[tid];

    // ATT row-constant factors for this thread's 2 staging rows
    float A1r[2], B1r[2];
    const int* adjA = adj;
    const float* s2A = s2lp;
    if (ATT) {
        adjA = adj + (long long)bz * NN * NN;
        s2A = s2lp + (long long)z2 * NN;
#pragma unroll
        for (int p = 0; p < 2; p++) {
            const long long ridx = (long long)z2 * NN + bm + arow0 + p * 64;
            A1r[p] = a1p[ridx];
            B1r[p] = b1p[ridx];
        }
    }

    float acc[2][8][4];
#pragma unroll
    for (int i = 0; i < 2; i++)
#pragma unroll
        for (int j = 0; j < 8; j++)
#pragma unroll
            for (int r = 0; r < 4; r++) acc[i][j][r] = 0.f;

    // ---- prologue: stage tile 0 ----
    if (ATT) {
        const int mg = soff + ac * 4;
        const float4 sv = *(const float4*)(s2A + mg);
#pragma unroll
        for (int p = 0; p < 2; p++) {
            const int row = arow0 + p * 64;
            const int4 aj = *(const int4*)(adjA + (long long)(bm + row) * NN + mg);
            As[0][row][aw0 + 0] = att_val(aj.x, sv.x, A1r[p], B1r[p]);
            As[0][row][aw0 + 2] = att_val(aj.y, sv.y, A1r[p], B1r[p]);
            As[0][row][aw0 + 4] = att_val(aj.z, sv.z, A1r[p], B1r[p]);
            As[0][row][aw0 + 6] = att_val(aj.w, sv.w, A1r[p], B1r[p]);
        }
    } else {
#pragma unroll
        for (int p = 0; p < 2; p++) {
            const int row = arow0 + p * 64;
            const float4 av = *(const float4*)(A + (long long)(bm + row) * Kfull + ac * 4);
            As[0][row][aw0 + 0] = rtf(av.x);
            As[0][row][aw0 + 2] = rtf(av.y);
            As[0][row][aw0 + 4] = rtf(av.z);
            As[0][row][aw0 + 6] = rtf(av.w);
        }
    }
#pragma unroll
    for (int p = 0; p < 2; p++) {
        const int rr = br + p * 8;
        const float4 bv = *(const float4*)(B + (long long)rr * 128 + bc);
#pragma unroll
        for (int j = 0; j < 4; j++) {
            const int n = bc + j;
            const int sn = ((n >> 3) & 7) + ((n & 7) << 3) + (n & 64);
            Bs[0][rr][sn] = rtf(j == 0 ? bv.x : j == 1 ? bv.y : j == 2 ? bv.z : bv.w);
        }
    }
    __syncthreads();

    int buf = 0;
#pragma unroll 2
    for (int k0 = 0; k0 < KC; k0 += GBK) {
        const bool pre = (k0 + GBK) < KC;
        float4 pa[2], pb[2];
        int4 paj[2];
        float4 psv;
        if (pre) {
            const int kn = k0 + GBK;
            if (ATT) {
                const int mg = soff + kn + ac * 4;
                psv = *(const float4*)(s2A + mg);
#pragma unroll
                for (int p = 0; p < 2; p++)
                    paj[p] = *(const int4*)(adjA + (long long)(bm + arow0 + p * 64) * NN + mg);
            } else {
#pragma unroll
                for (int p = 0; p < 2; p++) {
                    const int row = arow0 + p * 64;
                    pa[p] = *(const float4*)(A + (long long)(bm + row) * Kfull + kn + ac * 4);
                }
            }
#pragma unroll
            for (int p = 0; p < 2; p++) {
                const int rr = br + p * 8;
                pb[p] = *(const float4*)(B + (long long)(kn + rr) * 128 + bc);
            }
        }

        // ---- compute on current buffer ----
#pragma unroll
        for (int ks = 0; ks < GBK; ks += 8) {
            const unsigned* r0 = &Bs[buf][ks + q][0];
            const unsigned* r1 = &Bs[buf][ks + q + 4][0];
            const uint4 b0a = *(const uint4*)(r0 + wn + 8 * g);
            const uint4 b0b = *(const uint4*)(r0 + wn + 8 * g + 4);
            const uint4 b1a = *(const uint4*)(r1 + wn + 8 * g);
            const uint4 b1b = *(const uint4*)(r1 + wn + 8 * g + 4);
            const unsigned bu0[8] = {b0a.x, b0a.y, b0a.z, b0a.w, b0b.x, b0b.y, b0b.z, b0b.w};
            const unsigned bu1[8] = {b1a.x, b1a.y, b1a.z, b1a.w, b1b.x, b1b.y, b1b.z, b1b.w};
            unsigned af[2][4];
#pragma unroll
            for (int mt = 0; mt < 2; mt++) {
                const int m0 = wm + mt * 16 + g;
                const uint2 a0 = *(const uint2*)&As[buf][m0][ks + 2 * q];
                const uint2 a1 = *(const uint2*)&As[buf][m0 + 8][ks + 2 * q];
                af[mt][0] = a0.x; af[mt][1] = a1.x; af[mt][2] = a0.y; af[mt][3] = a1.y;
            }
#pragma unroll
            for (int mt = 0; mt < 2; mt++)
#pragma unroll
                for (int nt = 0; nt < 8; nt++)
                    mma_tf32(acc[mt][nt], af[mt], bu0[nt], bu1[nt]);
        }

        // ---- stage next tile ----
        if (pre) {
            const int nb = buf ^ 1;
            if (ATT) {
#pragma unroll
                for (int p = 0; p < 2; p++) {
                    const int row = arow0 + p * 64;
                    As[nb][row][aw0 + 0] = att_val(paj[p].x, psv.x, A1r[p], B1r[p]);
                    As[nb][row][aw0 + 2] = att_val(paj[p].y, psv.y, A1r[p], B1r[p]);
                    As[nb][row][aw0 + 4] = att_val(paj[p].z, psv.z, A1r[p], B1r[p]);
                    As[nb][row][aw0 + 6] = att_val(paj[p].w, psv.w, A1r[p], B1r[p]);
                }
            } else {
#pragma unroll
                for (int p = 0; p < 2; p++) {
                    const int row = arow0 + p * 64;
                    As[nb][row][aw0 + 0] = rtf(pa[p].x);
                    As[nb][row][aw0 + 2] = rtf(pa[p].y);
                    As[nb][row][aw0 + 4] = rtf(pa[p].z);
                    As[nb][row][aw0 + 6] = rtf(pa[p].w);
                }
            }
#pragma unroll
            for (int p = 0; p < 2; p++) {
                const int rr = br + p * 8;
#pragma unroll
                for (int j = 0; j < 4; j++) {
                    const int n = bc + j;
                    const int sn = ((n >> 3) & 7) + ((n & 7) << 3) + (n & 64);
                    Bs[nb][rr][sn] = rtf(j == 0 ? pb[p].x : j == 1 ? pb[p].y : j == 2 ? pb[p].z : pb[p].w);
                }
            }
            __syncthreads();
            buf = nb;
        }
    }

    // ---- epilogue ----
    float p1[2][2], p2[2][2];
    if (EPI == 2) {
#pragma unroll
        for (int mt = 0; mt < 2; mt++)
#pragma unroll
            for (int hf = 0; hf < 2; hf++) { p1[mt][hf] = 0.f; p2[mt][hf] = 0.f; }
    }
#pragma unroll
    for (int mt = 0; mt < 2; mt++) {
#pragma unroll
        for (int half = 0; half < 2; half++) {
            const int row = wm + mt * 16 + g + half * 8;
            if (S == 1) {
                float* crow = C + (long long)(bm + row) * ldc;
#pragma unroll
                for (int nt = 0; nt < 8; nt++) {
                    const int col = wn + nt * 8 + 2 * q;
                    float v0 = acc[mt][nt][half * 2 + 0];
                    float v1 = acc[mt][nt][half * 2 + 1];
                    if (EPI == 1) {
                        v0 = v0 > 0.f ? v0 : (__expf(v0) - 1.f);
                        v1 = v1 > 0.f ? v1 : (__expf(v1) - 1.f);
                    }
                    if (EPI == 2) {
                        p1[mt][half] += v0 * ash[col] + v1 * ash[col + 1];
                        p2[mt][half] += v0 * ash[FF + col] + v1 * ash[FF + col + 1];
                    }
                    *(float2*)(crow + col) = make_float2(v0, v1);
                }
            } else {
                float* prow = Cpart + (long long)s * TOT + ((long long)z2 * M + bm + row) * 128;
#pragma unroll
                for (int nt = 0; nt < 8; nt++) {
                    const int col = wn + nt * 8 + 2 * q;
                    *(float2*)(prow + col) = make_float2(acc[mt][nt][half * 2 + 0],
                                                         acc[mt][nt][half * 2 + 1]);
                }
            }
        }
    }

    if (EPI == 2) {
#pragma unroll
        for (int mt = 0; mt < 2; mt++)
#pragma unroll
            for (int hf = 0; hf < 2; hf++) {
                p1[mt][hf] += __shfl_xor_sync(0xffffffffu, p1[mt][hf], 1);
                p1[mt][hf] += __shfl_xor_sync(0xffffffffu, p1[mt][hf], 2);
                p2[mt][hf] += __shfl_xor_sync(0xffffffffu, p2[mt][hf], 1);
                p2[mt][hf] += __shfl_xor_sync(0xffffffffu, p2[mt][hf], 2);
            }
        __syncthreads();
        if ((wid >> 2) == 0 && q == 0) {
#pragma unroll
            for (int mt = 0; mt < 2; mt++)
#pragma unroll
                for (int hf = 0; hf < 2; hf++) {
                    const int r = wm + mt * 16 + hf * 8 + g;
                    sv1[r] = p1[mt][hf];
                    sv2[r] = p2[mt][hf];
                }
        }
        __syncthreads();
        if ((wid >> 2) == 1 && q == 0) {
#pragma unroll
            for (int mt = 0; mt < 2; mt++)
#pragma unroll
                for (int hf = 0; hf < 2; hf++) {
                    const int r = wm + mt * 16 + hf * 8 + g;
                    const long long oidx = (long long)z2 * NN + bm + r;
                    o1[oidx] = sv1[r] + p1[mt][hf];
                    o2[oidx] = sv2[r] + p2[mt][hf];
                }
        }
    }
}

// ---------------- row stats: log2-domain attention factors ----------------
__global__ void k_stats(const int* __restrict__ adj, const float* __restrict__ s1,
                        const float* __restrict__ s2, float* __restrict__ a1,
                        float* __restrict__ b1, float* __restrict__ s2l, int Hb) {
    const int n = blockIdx.x, h = blockIdx.y, b = blockIdx.z;
    const int t = threadIdx.x;
    const int m0 = t * 4;
    const int* adjrow = adj + ((long)b * NN + n) * NN;
    const long idx = ((long)b * Hb + h) * NN + n;
    const float* s2row = s2 + ((long)b * Hb + h) * NN;
    const float s1v = s1[idx];

    const int4 aj = *(const int4*)(adjrow + m0);
    const float4 sv = *(const float4*)(s2row + m0);

    float v[4];
    {
        float e0 = s1v + sv.x; e0 = e0 > 0.f ? e0 : 0.2f * e0; v[0] = (aj.x > 0) ? e0 : NEGV;
        float e1 = s1v + sv.y; e1 = e1 > 0.f ? e1 : 0.2f * e1; v[1] = (aj.y > 0) ? e1 : NEGV;
        float e2 = s1v + sv.z; e2 = e2 > 0.f ? e2 : 0.2f * e2; v[2] = (aj.z > 0) ? e2 : NEGV;
        float e3 = s1v + sv.w; e3 = e3 > 0.f ? e3 : 0.2f * e3; v[3] = (aj.w > 0) ? e3 : NEGV;
    }
    float mv = fmaxf(fmaxf(v[0], v[1]), fmaxf(v[2], v[3]));
    mv = blockMax128(mv);
    float sum = 0.f;
#pragma unroll
    for (int j = 0; j < 4; j++) sum += __expf(v[j] - mv);
    sum = blockSum128(sum);
    if (t == 0) {
        const float li = -__log2f(sum);
        a1[idx] = (s1v - mv) * LOG2E + li;
        b1[idx] = (0.2f * s1v - mv) * LOG2E + li;
        s2l[idx] = s2[idx] * LOG2E;
    }
}

// ---------------- split-K(2) reduce + ELU + scatter into multi[b,n,h*F+f] ----------------
// part layout: s*TOT3 + ((b*HH+h)*NN + n)*FF + f ; flat grid, float4 per thread.
__global__ void k_red_elu(const float* __restrict__ part, float* __restrict__ multi,
                          long long TOT3) {
    const long long i4 = ((long long)blockIdx.x * 256 + threadIdx.x) * 4;
    float4 a = *(const float4*)(part + i4);
    const float4 b = *(const float4*)(part + TOT3 + i4);
    a.x += b.x; a.y += b.y; a.z += b.z; a.w += b.w;
    a.x = a.x > 0.f ? a.x : (__expf(a.x) - 1.f);
    a.y = a.y > 0.f ? a.y : (__expf(a.y) - 1.f);
    a.z = a.z > 0.f ? a.z : (__expf(a.z) - 1.f);
    a.w = a.w > 0.f ? a.w : (__expf(a.w) - 1.f);
    // decompose i4 -> (b,h,n,f)
    const int f = (int)(i4 & (FF - 1));
    const long long r = i4 >> 7;            // (b*HH+h)*NN + n
    const int n = (int)(r & (NN - 1));
    const long long bh = r >> 9;            // b*HH + h
    const int hz = (int)(bh & (HH - 1));
    const long long bz = bh >> 3;
    float* dst = multi + ((bz * NN + n) * HH + hz) * FF + f;
    *(float4*)dst = a;
}

// ---------------- fused split-K(4) reduce + svec ----------------
__global__ void k_red_svec(const float* __restrict__ part, float* __restrict__ h2,
                           const float* __restrict__ a, float* __restrict__ t1,
                           float* __restrict__ t2, long long TOT) {
    const int row = blockIdx.x;
    const int t = threadIdx.x;
    const long long i = (long long)row * FF + t;
    float v = part[i] + (part[TOT + i] + part[2 * TOT + i] + part[3 * TOT + i]);
    h2[i] = v;
    float p1 = v * a[t];
    float p2 = v * a[FF + t];
    p1 = blockSum128(p1);
    p2 = blockSum128(p2);
    if (t == 0) {
        t1[row] = p1;
        t2[row] = p2;
    }
}

// ---------------- fused split-K(4) reduce + residual + layernorm (+relu) ----------------
__global__ void k_red_lnorm(const float* __restrict__ part, const float* __restrict__ res,
                            const float* __restrict__ g, const float* __restrict__ bb,
                            float* __restrict__ dst, int do_relu, long long TOT) {
    const int row = blockIdx.x;
    const int t = threadIdx.x;
    const long long i = (long long)row * FF + t;
    const float o = part[i] + (part[TOT + i] + part[2 * TOT + i] + part[3 * TOT + i]);
    const float y = o + res[i];
    const float mu = blockSum128(y) * (1.f / FF);
    const float d = y - mu;
    const float var = blockSum128(d * d) * (1.f / FF);
    float r = d * rsqrtf(var + 1e-5f) * g[t] + bb[t];
    if (do_relu) r = fmaxf(r, 0.f);
    dst[i] = r;
}

// ---------------- host orchestration ----------------
extern "C" void kernel_launch(void* const* d_in, const int* in_sizes, int n_in,
                              void* d_out, int out_size) {
    (void)in_sizes; (void)n_in; (void)out_size;
    const float* x       = (const float*)d_in[0];
    const int*   adj     = (const int*)  d_in[1];
    const float* Wp      = (const float*)d_in[2];
    const float* bp      = (const float*)d_in[3];
    const float* W_heads = (const float*)d_in[4];
    const float* a_heads = (const float*)d_in[5];
    const float* W_out   = (const float*)d_in[6];
    const float* a_out   = (const float*)d_in[7];
    const float* ln_g    = (const float*)d_in[8];
    const float* ln_b    = (const float*)d_in[9];
    float* out = (float*)d_out;

    float *p_h, *p_hh, *p_multi, *p_h2, *p_part;
    float *p_s1, *p_s2, *p_a1, *p_b1, *p_s2l, *p_t1, *p_t2;
    cudaGetSymbolAddress((void**)&p_h, g_h);
    cudaGetSymbolAddress((void**)&p_hh, g_hh);
    cudaGetSymbolAddress((void**)&p_multi, g_multi);
    cudaGetSymbolAddress((void**)&p_h2, g_h2);
    cudaGetSymbolAddress((void**)&p_part, g_part);
    cudaGetSymbolAddress((void**)&p_s1, g_s1);
    cudaGetSymbolAddress((void**)&p_s2, g_s2);
    cudaGetSymbolAddress((void**)&p_a1, g_a1);
    cudaGetSymbolAddress((void**)&p_b1, g_b1);
    cudaGetSymbolAddress((void**)&p_s2l, g_s2l);
    cudaGetSymbolAddress((void**)&p_t1, g_t1);
    cudaGetSymbolAddress((void**)&p_t2, g_t2);

    const long long TOT  = (long long)BATCH * NN * FF;        // 524288
    const long long TOT3 = (long long)BATCH * HH * NN * FF;   // 4194304

    k_proj<<<BATCH * NN, 128>>>(x, Wp, bp, p_h);

    for (int l = 0; l < LL; l++) {
        // 1) per-head projection + fused svec
        k_gemm_t<128, 1, 2, 0><<<dim3(1, NN / GBM, BATCH * HH), 256>>>(
            p_h, W_heads + (long)l * HH * FF * FF, p_hh, p_part,
            NN,
            (long long)NN * FF, 0,
            0, (long long)FF * FF,
            (long long)HH * NN * FF, (long long)NN * FF,
            HH, FF, 0,
            nullptr, nullptr, nullptr, nullptr,
            a_heads + (long)l * HH * 2 * FF, p_s1, p_s2);

        // 2) softmax factors (log2 domain)
        k_stats<<<dim3(NN, HH, BATCH), 128>>>(adj, p_s1, p_s2, p_a1, p_b1, p_s2l, HH);

        // 3) fused (softmax ∘ att) @ hh, split-K S=2 -> partials
        k_gemm_t<256, 2, 0, 1><<<dim3(1, NN / GBM, BATCH * HH * 2), 256>>>(
            nullptr, p_hh, nullptr, p_part,
            NN,
            0, 0,
            (long long)HH * NN * FF, (long long)NN * FF,
            0, 0,
            HH, FF, TOT3,
            adj, p_a1, p_b1, p_s2l,
            nullptr, nullptr, nullptr);
        // 3b) reduce + ELU + scatter into multi[b,n,h*F+f]
        k_red_elu<<<(int)(TOT3 / 4 / 256), 256>>>(p_part, p_multi, TOT3);

        // 4) out projection split-K S=4 + fused reduce+svec
        k_gemm_t<256, 4, 0, 0><<<dim3(1, (BATCH * NN) / GBM, 4), 256>>>(
            p_multi, W_out + (long)l * HH * FF * FF, p_h2, p_part,
            BATCH * NN,
            0, 0, 0, 0, 0, 0,
            1, FF, TOT,
            nullptr, nullptr, nullptr, nullptr,
            nullptr, nullptr, nullptr);
        k_red_svec<<<BATCH * NN, 128>>>(p_part, p_h2, a_out + (long)l * 2 * FF,
                                        p_t1, p_t2, TOT);

        // 5) single-head softmax factors
        k_stats<<<dim3(NN, 1, BATCH), 128>>>(adj, p_t1, p_t2, p_a1, p_b1, p_s2l, 1);

        // 6) fused (softmax ∘ att2) @ h2 split-K S=4 + fused reduce+residual+layernorm
        k_gemm_t<128, 4, 0, 1><<<dim3(1, NN / GBM, BATCH * 4), 256>>>(
            nullptr, p_h2, nullptr, p_part,
            NN,
            0, 0,
            (long long)NN * FF, 0,
            0, 0,
            1, FF, TOT,
            adj, p_a1, p_b1, p_s2l,
            nullptr, nullptr, nullptr);
        float* dst = (l == LL - 1) ? out : p_h;
        k_red_lnorm<<<BATCH * NN, 128>>>(p_part, p_h,
                                         ln_g + (long)l * FF, ln_b + (long)l * FF,
                                         dst, (l < LL - 1) ? 1 : 0, TOT);
    }
}

// round 12
// speedup vs baseline: 1.1215x; 1.1215x over previous
#include <cuda_runtime.h>
#include <cuda_bf16.h>
#include <math.h>

// ---------------- problem constants ----------------
#define BATCH 8
#define NN    512
#define DIN   64
#define HH    8
#define FF    128
#define LL    2
#define NEGV  (-9e15f)
#define LOG2E 1.4426950408889634f

// ---------------- scratch (device globals; no allocs) ----------------
__device__ float    g_h    [BATCH * NN * FF];
__device__ float    g_hh   [BATCH * HH * NN * FF];
__device__ float    g_multi[BATCH * NN * HH * FF];
__device__ float    g_h2   [BATCH * NN * FF];
__device__ float    g_part [8 * BATCH * NN * FF];     // split-K partials (S<=8)
__device__ unsigned g_adjp [BATCH * NN * 16];         // bit-packed adjacency
__device__ float    g_s1   [BATCH * HH * NN];
__device__ float    g_s2   [BATCH * HH * NN];
__device__ float    g_a1   [BATCH * HH * NN];         // (s1-mx)*log2e - log2(sum)
__device__ float    g_b1   [BATCH * HH * NN];         // (0.2 s1-mx)*log2e - log2(sum)
__device__ float    g_s2l  [BATCH * HH * NN];         // s2*log2e
__device__ float    g_t1   [BATCH * NN];
__device__ float    g_t2   [BATCH * NN];

// ---------------- reductions ----------------
__device__ __forceinline__ float warpSum(float v) {
#pragma unroll
    for (int o = 16; o > 0; o >>= 1) v += __shfl_xor_sync(0xffffffffu, v, o);
    return v;
}
__device__ __forceinline__ float warpMax(float v) {
#pragma unroll
    for (int o = 16; o > 0; o >>= 1) v = fmaxf(v, __shfl_xor_sync(0xffffffffu, v, o));
    return v;
}
__device__ __forceinline__ float blockSum128(float v) {
    __shared__ float sh[4];
    v = warpSum(v);
    __syncthreads();
    if ((threadIdx.x & 31) == 0) sh[threadIdx.x >> 5] = v;
    __syncthreads();
    return sh[0] + sh[1] + sh[2] + sh[3];
}
__device__ __forceinline__ float blockMax128(float v) {
    __shared__ float sh[4];
    v = warpMax(v);
    __syncthreads();
    if ((threadIdx.x & 31) == 0) sh[threadIdx.x >> 5] = v;
    __syncthreads();
    return fmaxf(fmaxf(sh[0], sh[1]), fmaxf(sh[2], sh[3]));
}

// ---------------- tf32 RNA rounding (bit trick == cvt.rna.tf32) ----------------
__device__ __forceinline__ unsigned rtf(float f) {
    return __float_as_uint(f) + 0x1000u;   // exact-0 stays 0 after 19-bit truncation
}
__device__ __forceinline__ void mma_tf32(float c[4], const unsigned a[4], const unsigned b0, const unsigned b1) {
    asm("mma.sync.aligned.m16n8k8.row.col.f32.tf32.tf32.f32 "
        "{%0,%1,%2,%3},{%4,%5,%6,%7},{%8,%9},{%0,%1,%2,%3};"
        : "+f"(c[0]), "+f"(c[1]), "+f"(c[2]), "+f"(c[3])
        : "r"(a[0]), "r"(a[1]), "r"(a[2]), "r"(a[3]), "r"(b0), "r"(b1));
}
__device__ __forceinline__ float ex2f(float x) {
    float r;
    asm("ex2.approx.f32 %0, %1;" : "=f"(r) : "f"(x));
    return r;
}
// att element in log2 domain: bit ? ex2(max(A1+s2l, fma(0.2,s2l,B1))) : 0
__device__ __forceinline__ unsigned att_val(unsigned bit, float s2l, float A1, float B1) {
    const float arg = fmaxf(A1 + s2l, fmaf(0.2f, s2l, B1));
    const float r = bit ? ex2f(arg) : 0.f;
    return rtf(r);
}

// ---------------- adjacency bit-pack (one-time) ----------------
__global__ void k_pack(const int* __restrict__ adj, unsigned* __restrict__ packed) {
    const long long row = blockIdx.x;       // b*NN + n
    const int t = threadIdx.x;              // 0..127
    const int w = t >> 5, lane = t & 31;
#pragma unroll
    for (int p = 0; p < 4; p++) {
        const int col = p * 128 + w * 32 + lane;
        const unsigned m = __ballot_sync(0xffffffffu, adj[row * NN + col] > 0);
        if (lane == 0) packed[row * 16 + p * 4 + w] = m;
    }
}

// ---------------- input projection ----------------
__global__ void k_proj(const float* __restrict__ x, const float* __restrict__ Wp,
                       const float* __restrict__ bp, float* __restrict__ h) {
    __shared__ float xs[DIN];
    const int row = blockIdx.x;
    const int t = threadIdx.x;
    if (t < DIN) xs[t] = x[(long)row * DIN + t];
    __syncthreads();
    float acc = bp[t];
#pragma unroll
    for (int i = 0; i < DIN; i++) acc = fmaf(xs[i], Wp[i * FF + t], acc);
    h[(long)row * FF + t] = fmaxf(acc, 0.f);
}

// ---------------- pipelined TF32 tensor-core GEMM ----------------
// C[M,128] = A[M,KC*S] @ B[KC*S,128], row-major, ldb = 128.
// Block tile 128x128, K-step 16, double-buffered smem, 8 warps 4(M)x2(N).
// EPI: 0 none, 1 ELU, 2 plain + fused svec. ATT: 1 = A computed from log2 att factors.
#define GBM 128
#define GBK 16
#define ALD 24
#define BLD 136
template <int KC, int S, int EPI, int ATT>
__global__ __launch_bounds__(256, 2)
void k_gemm_t(const float* __restrict__ A, const float* __restrict__ B,
              float* __restrict__ C, float* __restrict__ Cpart,
              int M,
              long long sAb, long long sAh,
              long long sBb, long long sBh,
              long long sCb, long long sCh,
              int Hb, int ldc, long long TOT,
              const unsigned* __restrict__ adjp,
              const float* __restrict__ a1p, const float* __restrict__ b1p,
              const float* __restrict__ s2lp,
              const float* __restrict__ avec,
              float* __restrict__ o1, float* __restrict__ o2) {
    const int zz = blockIdx.z;
    const int s = zz % S;
    const int z2 = zz / S;
    const int bz = z2 / Hb, hz = z2 % Hb;
    A += bz * sAb + hz * sAh + (long long)s * KC;
    B += bz * sBb + hz * sBh + (long long)s * KC * 128;
    C += bz * sCb + hz * sCh;
    const int bm = blockIdx.y * GBM;
    constexpr long long Kfull = (long long)KC * S;
    const int soff = s * KC;

    __shared__ unsigned As[2][GBM][ALD];   // [m][perm_k]
    __shared__ unsigned Bs[2][GBK][BLD];   // [k][perm_n]
    __shared__ float ash[2 * FF];          // EPI==2
    __shared__ float sv1[GBM], sv2[GBM];   // EPI==2

    const int tid  = threadIdx.x;
    const int lane = tid & 31;
    const int wid  = tid >> 5;
    const int wm = (wid & 3) * 32;
    const int wn = (wid >> 2) * 64;
    const int q = lane & 3;
    const int g = lane >> 2;

    const int arow0 = tid >> 2;
    const int ac = tid & 3;
    const int aw0 = (ac & 1) + 8 * (ac >> 1);
    const int br = tid >> 5;
    const int bc = lane * 4;

    if (EPI == 2 && tid < 2 * FF) ash[tid] = (avec + (long long)hz * 2 * FF)[tid];

    // ATT row-constant factors for this thread's 2 staging rows
    float A1r[2], B1r[2];
    const unsigned* adjP = adjp;
    const float* s2A = s2lp;
    if (ATT) {
        adjP = adjp + (long long)bz * NN * 16;
        s2A = s2lp + (long long)z2 * NN;
#pragma unroll
        for (int p = 0; p < 2; p++) {
            const long long ridx = (long long)z2 * NN + bm + arow0 + p * 64;
            A1r[p] = a1p[ridx];
            B1r[p] = b1p[ridx];
        }
    }

    float acc[2][8][4];
#pragma unroll
    for (int i = 0; i < 2; i++)
#pragma unroll
        for (int j = 0; j < 8; j++)
#pragma unroll
            for (int r = 0; r < 4; r++) acc[i][j][r] = 0.f;

    // ---- prologue: stage tile 0 ----
    if (ATT) {
        const int mg = soff + ac * 4;
        const float4 sv = *(const float4*)(s2A + mg);
        const int wix = mg >> 5, bo = mg & 31;
#pragma unroll
        for (int p = 0; p < 2; p++) {
            const int row = arow0 + p * 64;
            const unsigned w = adjP[(long long)(bm + row) * 16 + wix];
            As[0][row][aw0 + 0] = att_val((w >> (bo + 0)) & 1u, sv.x, A1r[p], B1r[p]);
            As[0][row][aw0 + 2] = att_val((w >> (bo + 1)) & 1u, sv.y, A1r[p], B1r[p]);
            As[0][row][aw0 + 4] = att_val((w >> (bo + 2)) & 1u, sv.z, A1r[p], B1r[p]);
            As[0][row][aw0 + 6] = att_val((w >> (bo + 3)) & 1u, sv.w, A1r[p], B1r[p]);
        }
    } else {
#pragma unroll
        for (int p = 0; p < 2; p++) {
            const int row = arow0 + p * 64;
            const float4 av = *(const float4*)(A + (long long)(bm + row) * Kfull + ac * 4);
            As[0][row][aw0 + 0] = rtf(av.x);
            As[0][row][aw0 + 2] = rtf(av.y);
            As[0][row][aw0 + 4] = rtf(av.z);
            As[0][row][aw0 + 6] = rtf(av.w);
        }
    }
#pragma unroll
    for (int p = 0; p < 2; p++) {
        const int rr = br + p * 8;
        const float4 bv = *(const float4*)(B + (long long)rr * 128 + bc);
#pragma unroll
        for (int j = 0; j < 4; j++) {
            const int n = bc + j;
            const int sn = ((n >> 3) & 7) + ((n & 7) << 3) + (n & 64);
            Bs[0][rr][sn] = rtf(j == 0 ? bv.x : j == 1 ? bv.y : j == 2 ? bv.z : bv.w);
        }
    }
    __syncthreads();

    int buf = 0;
#pragma unroll 2
    for (int k0 = 0; k0 < KC; k0 += GBK) {
        const bool pre = (k0 + GBK) < KC;
        float4 pa[2], pb[2];
        unsigned paw[2];
        float4 psv;
        if (pre) {
            const int kn = k0 + GBK;
            if (ATT) {
                const int mg = soff + kn + ac * 4;
                psv = *(const float4*)(s2A + mg);
                const int wix = mg >> 5;
#pragma unroll
                for (int p = 0; p < 2; p++)
                    paw[p] = adjP[(long long)(bm + arow0 + p * 64) * 16 + wix];
            } else {
#pragma unroll
                for (int p = 0; p < 2; p++) {
                    const int row = arow0 + p * 64;
                    pa[p] = *(const float4*)(A + (long long)(bm + row) * Kfull + kn + ac * 4);
                }
            }
#pragma unroll
            for (int p = 0; p < 2; p++) {
                const int rr = br + p * 8;
                pb[p] = *(const float4*)(B + (long long)(kn + rr) * 128 + bc);
            }
        }

        // ---- compute on current buffer ----
#pragma unroll
        for (int ks = 0; ks < GBK; ks += 8) {
            const unsigned* r0 = &Bs[buf][ks + q][0];
            const unsigned* r1 = &Bs[buf][ks + q + 4][0];
            const uint4 b0a = *(const uint4*)(r0 + wn + 8 * g);
            const uint4 b0b = *(const uint4*)(r0 + wn + 8 * g + 4);
            const uint4 b1a = *(const uint4*)(r1 + wn + 8 * g);
            const uint4 b1b = *(const uint4*)(r1 + wn + 8 * g + 4);
            const unsigned bu0[8] = {b0a.x, b0a.y, b0a.z, b0a.w, b0b.x, b0b.y, b0b.z, b0b.w};
            const unsigned bu1[8] = {b1a.x, b1a.y, b1a.z, b1a.w, b1b.x, b1b.y, b1b.z, b1b.w};
            unsigned af[2][4];
#pragma unroll
            for (int mt = 0; mt < 2; mt++) {
                const int m0 = wm + mt * 16 + g;
                const uint2 a0 = *(const uint2*)&As[buf][m0][ks + 2 * q];
                const uint2 a1 = *(const uint2*)&As[buf][m0 + 8][ks + 2 * q];
                af[mt][0] = a0.x; af[mt][1] = a1.x; af[mt][2] = a0.y; af[mt][3] = a1.y;
            }
#pragma unroll
            for (int mt = 0; mt < 2; mt++)
#pragma unroll
                for (int nt = 0; nt < 8; nt++)
                    mma_tf32(acc[mt][nt], af[mt], bu0[nt], bu1[nt]);
        }

        // ---- stage next tile ----
        if (pre) {
            const int nb = buf ^ 1;
            if (ATT) {
                const int bo = (soff + k0 + GBK + ac * 4) & 31;
#pragma unroll
                for (int p = 0; p < 2; p++) {
                    const int row = arow0 + p * 64;
                    As[nb][row][aw0 + 0] = att_val((paw[p] >> (bo + 0)) & 1u, psv.x, A1r[p], B1r[p]);
                    As[nb][row][aw0 + 2] = att_val((paw[p] >> (bo + 1)) & 1u, psv.y, A1r[p], B1r[p]);
                    As[nb][row][aw0 + 4] = att_val((paw[p] >> (bo + 2)) & 1u, psv.z, A1r[p], B1r[p]);
                    As[nb][row][aw0 + 6] = att_val((paw[p] >> (bo + 3)) & 1u, psv.w, A1r[p], B1r[p]);
                }
            } else {
#pragma unroll
                for (int p = 0; p < 2; p++) {
                    const int row = arow0 + p * 64;
                    As[nb][row][aw0 + 0] = rtf(pa[p].x);
                    As[nb][row][aw0 + 2] = rtf(pa[p].y);
                    As[nb][row][aw0 + 4] = rtf(pa[p].z);
                    As[nb][row][aw0 + 6] = rtf(pa[p].w);
                }
            }
#pragma unroll
            for (int p = 0; p < 2; p++) {
                const int rr = br + p * 8;
#pragma unroll
                for (int j = 0; j < 4; j++) {
                    const int n = bc + j;
                    const int sn = ((n >> 3) & 7) + ((n & 7) << 3) + (n & 64);
                    Bs[nb][rr][sn] = rtf(j == 0 ? pb[p].x : j == 1 ? pb[p].y : j == 2 ? pb[p].z : pb[p].w);
                }
            }
            __syncthreads();
            buf = nb;
        }
    }

    // ---- epilogue ----
    float p1[2][2], p2[2][2];
    if (EPI == 2) {
#pragma unroll
        for (int mt = 0; mt < 2; mt++)
#pragma unroll
            for (int hf = 0; hf < 2; hf++) { p1[mt][hf] = 0.f; p2[mt][hf] = 0.f; }
    }
#pragma unroll
    for (int mt = 0; mt < 2; mt++) {
#pragma unroll
        for (int half = 0; half < 2; half++) {
            const int row = wm + mt * 16 + g + half * 8;
            if (S == 1) {
                float* crow = C + (long long)(bm + row) * ldc;
#pragma unroll
                for (int nt = 0; nt < 8; nt++) {
                    const int col = wn + nt * 8 + 2 * q;
                    float v0 = acc[mt][nt][half * 2 + 0];
                    float v1 = acc[mt][nt][half * 2 + 1];
                    if (EPI == 1) {
                        v0 = v0 > 0.f ? v0 : (__expf(v0) - 1.f);
                        v1 = v1 > 0.f ? v1 : (__expf(v1) - 1.f);
                    }
                    if (EPI == 2) {
                        p1[mt][half] += v0 * ash[col] + v1 * ash[col + 1];
                        p2[mt][half] += v0 * ash[FF + col] + v1 * ash[FF + col + 1];
                    }
                    *(float2*)(crow + col) = make_float2(v0, v1);
                }
            } else {
                float* prow = Cpart + (long long)s * TOT + ((long long)z2 * M + bm + row) * 128;
#pragma unroll
                for (int nt = 0; nt < 8; nt++) {
                    const int col = wn + nt * 8 + 2 * q;
                    *(float2*)(prow + col) = make_float2(acc[mt][nt][half * 2 + 0],
                                                         acc[mt][nt][half * 2 + 1]);
                }
            }
        }
    }

    if (EPI == 2) {
#pragma unroll
        for (int mt = 0; mt < 2; mt++)
#pragma unroll
            for (int hf = 0; hf < 2; hf++) {
                p1[mt][hf] += __shfl_xor_sync(0xffffffffu, p1[mt][hf], 1);
                p1[mt][hf] += __shfl_xor_sync(0xffffffffu, p1[mt][hf], 2);
                p2[mt][hf] += __shfl_xor_sync(0xffffffffu, p2[mt][hf], 1);
                p2[mt][hf] += __shfl_xor_sync(0xffffffffu, p2[mt][hf], 2);
            }
        __syncthreads();
        if ((wid >> 2) == 0 && q == 0) {
#pragma unroll
            for (int mt = 0; mt < 2; mt++)
#pragma unroll
                for (int hf = 0; hf < 2; hf++) {
                    const int r = wm + mt * 16 + hf * 8 + g;
                    sv1[r] = p1[mt][hf];
                    sv2[r] = p2[mt][hf];
                }
        }
        __syncthreads();
        if ((wid >> 2) == 1 && q == 0) {
#pragma unroll
            for (int mt = 0; mt < 2; mt++)
#pragma unroll
                for (int hf = 0; hf < 2; hf++) {
                    const int r = wm + mt * 16 + hf * 8 + g;
                    const long long oidx = (long long)z2 * NN + bm + r;
                    o1[oidx] = sv1[r] + p1[mt][hf];
                    o2[oidx] = sv2[r] + p2[mt][hf];
                }
        }
    }
}

// ---------------- row stats: log2-domain attention factors ----------------
__global__ void k_stats(const int* __restrict__ adj, const float* __restrict__ s1,
                        const float* __restrict__ s2, float* __restrict__ a1,
                        float* __restrict__ b1, float* __restrict__ s2l, int Hb) {
    const int n = blockIdx.x, h = blockIdx.y, b = blockIdx.z;
    const int t = threadIdx.x;
    const int m0 = t * 4;
    const int* adjrow = adj + ((long)b * NN + n) * NN;
    const long idx = ((long)b * Hb + h) * NN + n;
    const float* s2row = s2 + ((long)b * Hb + h) * NN;
    const float s1v = s1[idx];

    const int4 aj = *(const int4*)(adjrow + m0);
    const float4 sv = *(const float4*)(s2row + m0);

    float v[4];
    {
        float e0 = s1v + sv.x; e0 = e0 > 0.f ? e0 : 0.2f * e0; v[0] = (aj.x > 0) ? e0 : NEGV;
        float e1 = s1v + sv.y; e1 = e1 > 0.f ? e1 : 0.2f * e1; v[1] = (aj.y > 0) ? e1 : NEGV;
        float e2 = s1v + sv.z; e2 = e2 > 0.f ? e2 : 0.2f * e2; v[2] = (aj.z > 0) ? e2 : NEGV;
        float e3 = s1v + sv.w; e3 = e3 > 0.f ? e3 : 0.2f * e3; v[3] = (aj.w > 0) ? e3 : NEGV;
    }
    float mv = fmaxf(fmaxf(v[0], v[1]), fmaxf(v[2], v[3]));
    mv = blockMax128(mv);
    float sum = 0.f;
#pragma unroll
    for (int j = 0; j < 4; j++) sum += __expf(v[j] - mv);
    sum = blockSum128(sum);
    if (t == 0) {
        const float li = -__log2f(sum);
        a1[idx] = (s1v - mv) * LOG2E + li;
        b1[idx] = (0.2f * s1v - mv) * LOG2E + li;
        s2l[idx] = s2[idx] * LOG2E;
    }
}

// ---------------- fused split-K(8) reduce + svec ----------------
__global__ void k_red_svec(const float* __restrict__ part, float* __restrict__ h2,
                           const float* __restrict__ a, float* __restrict__ t1,
                           float* __restrict__ t2, long long TOT) {
    const int row = blockIdx.x;
    const int t = threadIdx.x;
    const long long i = (long long)row * FF + t;
    float v = 0.f;
#pragma unroll
    for (int j = 0; j < 8; j++) v += part[(long long)j * TOT + i];
    h2[i] = v;
    float p1 = v * a[t];
    float p2 = v * a[FF + t];
    p1 = blockSum128(p1);
    p2 = blockSum128(p2);
    if (t == 0) {
        t1[row] = p1;
        t2[row] = p2;
    }
}

// ---------------- fused split-K(8) reduce + residual + layernorm (+relu) ----------------
__global__ void k_red_lnorm(const float* __restrict__ part, const float* __restrict__ res,
                            const float* __restrict__ g, const float* __restrict__ bb,
                            float* __restrict__ dst, int do_relu, long long TOT) {
    const int row = blockIdx.x;
    const int t = threadIdx.x;
    const long long i = (long long)row * FF + t;
    float o = 0.f;
#pragma unroll
    for (int j = 0; j < 8; j++) o += part[(long long)j * TOT + i];
    const float y = o + res[i];
    const float mu = blockSum128(y) * (1.f / FF);
    const float d = y - mu;
    const float var = blockSum128(d * d) * (1.f / FF);
    float r = d * rsqrtf(var + 1e-5f) * g[t] + bb[t];
    if (do_relu) r = fmaxf(r, 0.f);
    dst[i] = r;
}

// ---------------- host orchestration ----------------
extern "C" void kernel_launch(void* const* d_in, const int* in_sizes, int n_in,
                              void* d_out, int out_size) {
    (void)in_sizes; (void)n_in; (void)out_size;
    const float* x       = (const float*)d_in[0];
    const int*   adj     = (const int*)  d_in[1];
    const float* Wp      = (const float*)d_in[2];
    const float* bp      = (const float*)d_in[3];
    const float* W_heads = (const float*)d_in[4];
    const float* a_heads = (const float*)d_in[5];
    const float* W_out   = (const float*)d_in[6];
    const float* a_out   = (const float*)d_in[7];
    const float* ln_g    = (const float*)d_in[8];
    const float* ln_b    = (const float*)d_in[9];
    float* out = (float*)d_out;

    float *p_h, *p_hh, *p_multi, *p_h2, *p_part;
    float *p_s1, *p_s2, *p_a1, *p_b1, *p_s2l, *p_t1, *p_t2;
    unsigned* p_adjp;
    cudaGetSymbolAddress((void**)&p_h, g_h);
    cudaGetSymbolAddress((void**)&p_hh, g_hh);
    cudaGetSymbolAddress((void**)&p_multi, g_multi);
    cudaGetSymbolAddress((void**)&p_h2, g_h2);
    cudaGetSymbolAddress((void**)&p_part, g_part);
    cudaGetSymbolAddress((void**)&p_adjp, g_adjp);
    cudaGetSymbolAddress((void**)&p_s1, g_s1);
    cudaGetSymbolAddress((void**)&p_s2, g_s2);
    cudaGetSymbolAddress((void**)&p_a1, g_a1);
    cudaGetSymbolAddress((void**)&p_b1, g_b1);
    cudaGetSymbolAddress((void**)&p_s2l, g_s2l);
    cudaGetSymbolAddress((void**)&p_t1, g_t1);
    cudaGetSymbolAddress((void**)&p_t2, g_t2);

    const long long TOT = (long long)BATCH * NN * FF;   // 524288

    k_pack<<<BATCH * NN, 128>>>(adj, p_adjp);
    k_proj<<<BATCH * NN, 128>>>(x, Wp, bp, p_h);

    for (int l = 0; l < LL; l++) {
        // 1) per-head projection + fused svec
        k_gemm_t<128, 1, 2, 0><<<dim3(1, NN / GBM, BATCH * HH), 256>>>(
            p_h, W_heads + (long)l * HH * FF * FF, p_hh, p_part,
            NN,
            (long long)NN * FF, 0,
            0, (long long)FF * FF,
            (long long)HH * NN * FF, (long long)NN * FF,
            HH, FF, 0,
            nullptr, nullptr, nullptr, nullptr,
            a_heads + (long)l * HH * 2 * FF, p_s1, p_s2);

        // 2) softmax factors (log2 domain)
        k_stats<<<dim3(NN, HH, BATCH), 128>>>(adj, p_s1, p_s2, p_a1, p_b1, p_s2l, HH);

        // 3) fused (softmax ∘ att) @ hh, ELU, scatter into multi
        k_gemm_t<512, 1, 1, 1><<<dim3(1, NN / GBM, BATCH * HH), 256>>>(
            nullptr, p_hh, p_multi, p_part,
            NN,
            0, 0,
            (long long)HH * NN * FF, (long long)NN * FF,
            (long long)NN * HH * FF, (long long)FF,
            HH, HH * FF, 0,
            p_adjp, p_a1, p_b1, p_s2l,
            nullptr, nullptr, nullptr);

        // 4) out projection split-K S=8 + fused reduce+svec
        k_gemm_t<128, 8, 0, 0><<<dim3(1, (BATCH * NN) / GBM, 8), 256>>>(
            p_multi, W_out + (long)l * HH * FF * FF, p_h2, p_part,
            BATCH * NN,
            0, 0, 0, 0, 0, 0,
            1, FF, TOT,
            nullptr, nullptr, nullptr, nullptr,
            nullptr, nullptr, nullptr);
        k_red_svec<<<BATCH * NN, 128>>>(p_part, p_h2, a_out + (long)l * 2 * FF,
                                        p_t1, p_t2, TOT);

        // 5) single-head softmax factors
        k_stats<<<dim3(NN, 1, BATCH), 128>>>(adj, p_t1, p_t2, p_a1, p_b1, p_s2l, 1);

        // 6) fused (softmax ∘ att2) @ h2 split-K S=8 + fused reduce+residual+layernorm
        k_gemm_t<64, 8, 0, 1><<<dim3(1, NN / GBM, BATCH * 8), 256>>>(
            nullptr, p_h2, nullptr, p_part,
            NN,
            0, 0,
            (long long)NN * FF, 0,
            0, 0,
            1, FF, TOT,
            p_adjp, p_a1, p_b1, p_s2l,
            nullptr, nullptr, nullptr);
        float* dst = (l == LL - 1) ? out : p_h;
        k_red_lnorm<<<BATCH * NN, 128>>>(p_part, p_h,
                                         ln_g + (long)l * FF, ln_b + (long)l * FF,
                                         dst, (l < LL - 1) ? 1 : 0, TOT);
    }
}